// round 16
// baseline (speedup 1.0000x reference)
#include <cuda_runtime.h>
#include <cuda_bf16.h>
#include <mma.h>

using namespace nvcuda;

#define S_LEN 2048
#define NHIST 1024
#define LOCN 50000
#define D_LOCE 512
#define D_TIME 64
#define D_UIDE 64
#define HID 512
#define D_IN 576
#define TARGET 1024
#define GI_N 1536
#define OUTK 1088
#define GRU_BLOCKS 32

// ---------------- device scratch ----------------
// RULE: device globals are ONLY referenced inside kernels. Host code NEVER
// passes their address as a kernel argument (host symbol shadow + GB300 ATS
// silently reads/writes host memory -> zeros). Harness pointers only.
__device__ float g_x[S_LEN * D_IN];
__device__ float g_xcat[NHIST * D_IN];
__device__ float g_hist[NHIST * HID];
__device__ float g_gi[S_LEN * GI_N];
__device__ float g_h[2 * HID];
__device__ float g_q[TARGET * HID];
__device__ float g_scores[TARGET * NHIST];
__device__ float g_ctx[TARGET * HID];
__device__ __nv_bfloat16 g_outbh[TARGET * OUTK];
__device__ __nv_bfloat16 g_Wbh[(size_t)LOCN * OUTK];
__device__ int g_off[NHIST];
__device__ __align__(128) volatile unsigned g_flag[GRU_BLOCKS];

__global__ void k_init() {
    int t = threadIdx.x;
    for (int i = t; i < 2 * HID; i += blockDim.x) g_h[i] = 0.f;
    if (t < GRU_BLOCKS) g_flag[t] = 0u;
}

__global__ void k_offsets(const int* __restrict__ cnt) {
    __shared__ int sc[NHIST];
    int t = threadIdx.x;
    sc[t] = cnt[t];
    __syncthreads();
    int s = 0;
    for (int j = 0; j < t; j++) s += sc[j];
    g_off[t] = s;
}

__global__ void k_build_x(const int* __restrict__ loc, const int* __restrict__ tim,
                          const float* __restrict__ emb_loc, const float* __restrict__ emb_tim) {
    int idx = blockIdx.x * blockDim.x + threadIdx.x;
    if (idx >= S_LEN * D_IN) return;
    int s = idx / D_IN, d = idx - s * D_IN;
    float v;
    if (d < D_LOCE) v = emb_loc[(size_t)loc[s] * D_LOCE + d];
    else            v = emb_tim[(size_t)tim[s] * D_TIME + (d - D_LOCE)];
    g_x[idx] = v;
}

__global__ void k_hist_feat(const int* __restrict__ hloc, const int* __restrict__ htim,
                            const int* __restrict__ hcnt,
                            const float* __restrict__ emb_loc, const float* __restrict__ emb_tim) {
    int b = blockIdx.x, t = threadIdx.x;
    int off = g_off[b];
    int cnt = hcnt[b];
    float inv = (cnt > 0) ? 1.f / (float)cnt : 0.f;
    for (int d = t; d < D_LOCE; d += blockDim.x) {
        float s = 0.f;
        for (int r = 0; r < cnt; r++)
            s += emb_loc[(size_t)hloc[off + r] * D_LOCE + d];
        g_xcat[b * D_IN + d] = s * inv;
    }
    for (int d = t; d < D_TIME; d += blockDim.x)
        g_xcat[b * D_IN + D_LOCE + d] = emb_tim[(size_t)htim[off] * D_TIME + d];
}

// ---------------- tiled fp32 GEMM bodies (device-side; pointers bound by the
// CALLING KERNEL, never by host) ----------------
// C[M,N] = A[M,K] @ B[N,K]^T (+bias) (EPI 1 = tanh). M,N mult of 64, K mult of 16.
template <int EPI>
__device__ __forceinline__ void gemm_nt_body(const float* __restrict__ A,
                                             const float* __restrict__ B,
                                             const float* __restrict__ bias,
                                             float* __restrict__ C,
                                             int M, int N, int K) {
    __shared__ float As[16][64];
    __shared__ float Bs[16][64];
    int m0 = blockIdx.x * 64, n0 = blockIdx.y * 64;
    int t = threadIdx.x;
    int tx = t % 16, ty = t / 16;
    int lr = t / 4, lq = t % 4;
    float acc[4][4] = {};
    for (int k0 = 0; k0 < K; k0 += 16) {
        float4 av = *(const float4*)&A[(size_t)(m0 + lr) * K + k0 + lq * 4];
        float4 bv = *(const float4*)&B[(size_t)(n0 + lr) * K + k0 + lq * 4];
        As[lq * 4 + 0][lr] = av.x; As[lq * 4 + 1][lr] = av.y;
        As[lq * 4 + 2][lr] = av.z; As[lq * 4 + 3][lr] = av.w;
        Bs[lq * 4 + 0][lr] = bv.x; Bs[lq * 4 + 1][lr] = bv.y;
        Bs[lq * 4 + 2][lr] = bv.z; Bs[lq * 4 + 3][lr] = bv.w;
        __syncthreads();
#pragma unroll
        for (int k = 0; k < 16; k++) {
            float a[4], b[4];
#pragma unroll
            for (int i = 0; i < 4; i++) { a[i] = As[k][ty * 4 + i]; b[i] = Bs[k][tx * 4 + i]; }
#pragma unroll
            for (int i = 0; i < 4; i++)
#pragma unroll
                for (int j = 0; j < 4; j++) acc[i][j] += a[i] * b[j];
        }
        __syncthreads();
    }
#pragma unroll
    for (int i = 0; i < 4; i++)
#pragma unroll
        for (int j = 0; j < 4; j++) {
            int m = m0 + ty * 4 + i, n = n0 + tx * 4 + j;
            float v = acc[i][j];
            if (bias) v += bias[n];
            if (EPI == 1) v = tanhf(v);
            C[(size_t)m * N + n] = v;
        }
}

// C[M,N] = A[M,K] @ B[K,N]. M,N mult of 64, K mult of 16.
__device__ __forceinline__ void gemm_nn_body(const float* __restrict__ A,
                                             const float* __restrict__ B,
                                             float* __restrict__ C,
                                             int M, int N, int K) {
    __shared__ float As[16][64];
    __shared__ float Bs[16][64];
    int m0 = blockIdx.x * 64, n0 = blockIdx.y * 64;
    int t = threadIdx.x;
    int tx = t % 16, ty = t / 16;
    int lr = t / 4, lq = t % 4;
    int bk = t / 16, bn = t % 16;
    float acc[4][4] = {};
    for (int k0 = 0; k0 < K; k0 += 16) {
        float4 av = *(const float4*)&A[(size_t)(m0 + lr) * K + k0 + lq * 4];
        As[lq * 4 + 0][lr] = av.x; As[lq * 4 + 1][lr] = av.y;
        As[lq * 4 + 2][lr] = av.z; As[lq * 4 + 3][lr] = av.w;
        float4 bv = *(const float4*)&B[(size_t)(k0 + bk) * N + n0 + bn * 4];
        *(float4*)&Bs[bk][bn * 4] = bv;
        __syncthreads();
#pragma unroll
        for (int k = 0; k < 16; k++) {
            float a[4], b[4];
#pragma unroll
            for (int i = 0; i < 4; i++) { a[i] = As[k][ty * 4 + i]; b[i] = Bs[k][tx * 4 + i]; }
#pragma unroll
            for (int i = 0; i < 4; i++)
#pragma unroll
                for (int j = 0; j < 4; j++) acc[i][j] += a[i] * b[j];
        }
        __syncthreads();
    }
#pragma unroll
    for (int i = 0; i < 4; i++)
#pragma unroll
        for (int j = 0; j < 4; j++)
            C[(size_t)(m0 + ty * 4 + i) * N + n0 + tx * 4 + j] = acc[i][j];
}

// wrappers: device globals bound INSIDE the kernel; harness pointers as args
__global__ void __launch_bounds__(256) k_gemm_hist(const float* __restrict__ fa,
                                                   const float* __restrict__ fab) {
    gemm_nt_body<1>(g_xcat, fa, fab, g_hist, NHIST, HID, D_IN);
}
__global__ void __launch_bounds__(256) k_gemm_gi(const float* __restrict__ w_ih,
                                                 const float* __restrict__ b_ih) {
    gemm_nt_body<0>(g_x, w_ih, b_ih, g_gi, S_LEN, GI_N, D_IN);
}
__global__ void __launch_bounds__(256) k_gemm_scores() {
    gemm_nt_body<0>(g_q, g_hist, (const float*)0, g_scores, TARGET, NHIST, HID);
}
__global__ void __launch_bounds__(256) k_gemm_ctx() {
    gemm_nn_body(g_scores, g_hist, g_ctx, TARGET, HID, NHIST);
}

// ---------------- persistent GRU scan, flag-vector barrier ----------------
// 32 blocks x 256 threads. Block b owns hidden lanes [16b, 16b+16).
// rid = t/4 picks one of 48 gh rows, p = t%4 a 128-wide column quarter (regs).
// Barrier: block publishes g_flag[b] = step+1 after its h-slice store+fence;
// threads t<32 each poll one flag (one cache line, one transaction per poll).
__global__ void __launch_bounds__(256) k_gru(const float* __restrict__ w_hh,
                                             const float* __restrict__ b_hh) {
    __shared__ float h_s[HID];
    __shared__ float part[48][4];
    __shared__ float sgh[48];
    int b = blockIdx.x, t = threadIdx.x;
    int jbase = b * 16;
    int rid = t >> 2;
    int p = t & 3;
    bool active = (rid < 48);

    float wv[128];
    if (active) {
        int gate = rid >> 4;
        int jj = rid & 15;
        int grow = gate * HID + jbase + jj;
        const float* wr = w_hh + (size_t)grow * HID + p * 128;
#pragma unroll
        for (int i = 0; i < 128; i++) wv[i] = wr[i];
    }
    float bh0 = 0.f, bh1 = 0.f, bh2 = 0.f;
    if (t < 16) {
        bh0 = b_hh[jbase + t];
        bh1 = b_hh[HID + jbase + t];
        bh2 = b_hh[2 * HID + jbase + t];
    }

    for (int step = 0; step < S_LEN; step++) {
        float ir = 0.f, iz = 0.f, inn = 0.f;
        if (t < 16) {
            const float* git = g_gi + (size_t)step * GI_N;
            ir  = git[jbase + t];
            iz  = git[HID + jbase + t];
            inn = git[2 * HID + jbase + t];
        }
        const float* hrd = g_h + (step & 1) * HID;
        float* hwr = g_h + ((step + 1) & 1) * HID;
        if (t < 128) {
            float4 hv = __ldcg((const float4*)hrd + t);
            ((float4*)h_s)[t] = hv;
        }
        __syncthreads();

        if (active) {
            const float4* hp4 = (const float4*)(h_s + p * 128);
            float s0 = 0.f, s1 = 0.f, s2 = 0.f, s3 = 0.f;
#pragma unroll
            for (int i = 0; i < 32; i++) {
                float4 hv = hp4[i];
                s0 = fmaf(wv[4 * i + 0], hv.x, s0);
                s1 = fmaf(wv[4 * i + 1], hv.y, s1);
                s2 = fmaf(wv[4 * i + 2], hv.z, s2);
                s3 = fmaf(wv[4 * i + 3], hv.w, s3);
            }
            part[rid][p] = (s0 + s1) + (s2 + s3);
        }
        __syncthreads();
        if (t < 48) sgh[t] = (part[t][0] + part[t][1]) + (part[t][2] + part[t][3]);
        __syncthreads();

        if (t < 16) {
            float r = 1.f / (1.f + expf(-(ir + sgh[t] + bh0)));
            float z = 1.f / (1.f + expf(-(iz + sgh[16 + t] + bh1)));
            float n = tanhf(inn + r * (sgh[32 + t] + bh2));
            float hold = h_s[jbase + t];
            float hnew = (1.f - z) * n + z * hold;
            hwr[jbase + t] = hnew;
            if (step >= S_LEN - TARGET)
                g_q[(size_t)(step - (S_LEN - TARGET)) * HID + jbase + t] = hnew;
            __threadfence();
        }
        __syncthreads();
        if (t == 0) g_flag[b] = (unsigned)(step + 1);
        if (t < GRU_BLOCKS) {
            while (g_flag[t] < (unsigned)(step + 1)) {}
        }
        __threadfence();
        __syncthreads();
    }
}

// row softmax of scores [TARGET, NHIST]
__global__ void __launch_bounds__(256) k_softmax() {
    __shared__ float red[256];
    int r = blockIdx.x, t = threadIdx.x;
    float* row = g_scores + (size_t)r * NHIST;
    float m = -1e30f;
    for (int i = t; i < NHIST; i += 256) m = fmaxf(m, row[i]);
    red[t] = m; __syncthreads();
    for (int o = 128; o; o >>= 1) { if (t < o) red[t] = fmaxf(red[t], red[t + o]); __syncthreads(); }
    m = red[0];
    __syncthreads();
    float s = 0.f;
    for (int i = t; i < NHIST; i += 256) { float e = __expf(row[i] - m); row[i] = e; s += e; }
    red[t] = s; __syncthreads();
    for (int o = 128; o; o >>= 1) { if (t < o) red[t] += red[t + o]; __syncthreads(); }
    float inv = 1.f / red[0];
    for (int i = t; i < NHIST; i += 256) row[i] *= inv;
}

__global__ void k_build_out(const float* __restrict__ emb_uid, const int* __restrict__ uid) {
    int idx = blockIdx.x * blockDim.x + threadIdx.x;
    if (idx >= TARGET * OUTK) return;
    int r = idx / OUTK, c = idx - r * OUTK;
    float v;
    if (c < HID) v = g_q[(size_t)r * HID + c];
    else if (c < 2 * HID) v = g_ctx[(size_t)r * HID + (c - HID)];
    else v = emb_uid[(size_t)uid[0] * D_UIDE + (c - 2 * HID)];
    g_outbh[idx] = __float2bfloat16(v);
}

__global__ void k_convert_w(const float* __restrict__ W) {
    size_t n4 = (size_t)LOCN * OUTK / 4;
    for (size_t i = (size_t)blockIdx.x * blockDim.x + threadIdx.x; i < n4;
         i += (size_t)gridDim.x * blockDim.x) {
        float4 v = ((const float4*)W)[i];
        __nv_bfloat162* oh = (__nv_bfloat162*)g_Wbh;
        oh[2 * i]     = __floats2bfloat162_rn(v.x, v.y);
        oh[2 * i + 1] = __floats2bfloat162_rn(v.z, v.w);
    }
}

// ---------------- final bf16 wmma GEMM (single pass): Y = out @ W^T + bias ----
#define FBM 64
#define FBN 128
#define FBK 32
__global__ void __launch_bounds__(256) k_final(const float* __restrict__ bias, float* __restrict__ Y) {
    __shared__ __nv_bfloat16 As[FBM * FBK];
    __shared__ __nv_bfloat16 Bs[FBN * FBK];
    __shared__ float Cs[FBM * FBN];
    int m0 = blockIdx.x * FBM;
    int n0 = blockIdx.y * FBN;
    int t = threadIdx.x;
    int warp = t / 32;
    int wm = warp % 2, wn = warp / 2;

    wmma::fragment<wmma::accumulator, 16, 16, 16, float> acc[2][2];
#pragma unroll
    for (int i = 0; i < 2; i++)
#pragma unroll
        for (int j = 0; j < 2; j++) wmma::fill_fragment(acc[i][j], 0.f);

    for (int k0 = 0; k0 < OUTK; k0 += FBK) {
        {
            int r = t / 4, c = (t % 4) * 8;
            *(uint4*)&As[r * FBK + c] =
                *(const uint4*)&g_outbh[(size_t)(m0 + r) * OUTK + k0 + c];
        }
#pragma unroll
        for (int i = 0; i < 2; i++) {
            int idx = t + i * 256;
            int r = idx / 4, c = (idx % 4) * 8;
            int n = n0 + r;
            uint4 v = make_uint4(0u, 0u, 0u, 0u);
            if (n < LOCN)
                v = *(const uint4*)&g_Wbh[(size_t)n * OUTK + k0 + c];
            *(uint4*)&Bs[r * FBK + c] = v;
        }
        __syncthreads();
#pragma unroll
        for (int kk = 0; kk < FBK; kk += 16) {
            wmma::fragment<wmma::matrix_a, 16, 16, 16, __nv_bfloat16, wmma::row_major> a0, a1;
            wmma::fragment<wmma::matrix_b, 16, 16, 16, __nv_bfloat16, wmma::col_major> b0, b1;
            wmma::load_matrix_sync(a0, &As[(wm * 32 + 0) * FBK + kk], FBK);
            wmma::load_matrix_sync(a1, &As[(wm * 32 + 16) * FBK + kk], FBK);
            wmma::load_matrix_sync(b0, &Bs[(wn * 32 + 0) * FBK + kk], FBK);
            wmma::load_matrix_sync(b1, &Bs[(wn * 32 + 16) * FBK + kk], FBK);
            wmma::mma_sync(acc[0][0], a0, b0, acc[0][0]);
            wmma::mma_sync(acc[0][1], a0, b1, acc[0][1]);
            wmma::mma_sync(acc[1][0], a1, b0, acc[1][0]);
            wmma::mma_sync(acc[1][1], a1, b1, acc[1][1]);
        }
        __syncthreads();
    }
#pragma unroll
    for (int i = 0; i < 2; i++)
#pragma unroll
        for (int j = 0; j < 2; j++)
            wmma::store_matrix_sync(&Cs[(wm * 32 + i * 16) * FBN + wn * 32 + j * 16],
                                    acc[i][j], FBN, wmma::mem_row_major);
    __syncthreads();
    for (int idx = t; idx < FBM * FBN; idx += 256) {
        int r = idx / FBN, c = idx - r * FBN;
        int n = n0 + c;
        if (n < LOCN)
            Y[(size_t)(m0 + r) * LOCN + n] = Cs[idx] + bias[n];
    }
}

// ---------------- online (single-read) row log_softmax on Y [1024, 50000] ----
__global__ void __launch_bounds__(256) k_logsoftmax(float* __restrict__ Y) {
    __shared__ float rm[256], rs[256];
    int r = blockIdx.x, t = threadIdx.x;
    float* row = Y + (size_t)r * LOCN;
    const int n4 = LOCN / 4;
    float m = -1e30f, s = 0.f;
    for (int i = t; i < n4; i += 256) {
        float4 v = ((const float4*)row)[i];
        float mv = fmaxf(fmaxf(v.x, v.y), fmaxf(v.z, v.w));
        if (mv > m) { s *= __expf(m - mv); m = mv; }
        s += __expf(v.x - m) + __expf(v.y - m) + __expf(v.z - m) + __expf(v.w - m);
    }
    rm[t] = m; rs[t] = s; __syncthreads();
    for (int o = 128; o; o >>= 1) {
        if (t < o) {
            float m2 = fmaxf(rm[t], rm[t + o]);
            rs[t] = rs[t] * __expf(rm[t] - m2) + rs[t + o] * __expf(rm[t + o] - m2);
            rm[t] = m2;
        }
        __syncthreads();
    }
    float lse = rm[0] + logf(rs[0]);
    for (int i = t; i < n4; i += 256) {
        float4 v = ((float4*)row)[i];
        v.x -= lse; v.y -= lse; v.z -= lse; v.w -= lse;
        ((float4*)row)[i] = v;
    }
}

extern "C" void kernel_launch(void* const* d_in, const int* in_sizes, int n_in,
                              void* d_out, int out_size) {
    const int *loc = 0, *tim = 0, *hloc = 0, *htim = 0, *hcnt = 0, *uid = 0;
    const float *emb_loc = 0, *emb_tim = 0, *emb_uid = 0;
    const float *fc_attn_w = 0, *fc_attn_b = 0;
    const float *w_ih = 0, *w_hh = 0, *b_ih = 0, *b_hh = 0;
    const float *fc_final_w = 0, *fc_final_b = 0;
    int c2048 = 0, c4096 = 0, c1536 = 0, c1 = 0;
    for (int i = 0; i < n_in; i++) {
        long s = in_sizes[i];
        const void* p = d_in[i];
        if      (s == 2048)      { if (c2048++ == 0) loc = (const int*)p; else tim = (const int*)p; }
        else if (s == 4096)      { if (c4096++ == 0) hloc = (const int*)p; else htim = (const int*)p; }
        else if (s == 1024)      hcnt = (const int*)p;
        else if (s == 1)         { if (c1++ == 0) uid = (const int*)p; }
        else if (s == 25600000)  emb_loc = (const float*)p;
        else if (s == 3072)      emb_tim = (const float*)p;
        else if (s == 64000)     emb_uid = (const float*)p;
        else if (s == 294912)    fc_attn_w = (const float*)p;
        else if (s == 512)       fc_attn_b = (const float*)p;
        else if (s == 884736)    w_ih = (const float*)p;
        else if (s == 786432)    w_hh = (const float*)p;
        else if (s == 1536)      { if (c1536++ == 0) b_ih = (const float*)p; else b_hh = (const float*)p; }
        else if (s == 54400000)  fc_final_w = (const float*)p;
        else if (s == 50000)     fc_final_b = (const float*)p;
    }
    float* Y = (float*)d_out;

    k_init<<<1, 256>>>();
    k_offsets<<<1, NHIST>>>(hcnt);
    k_build_x<<<(S_LEN * D_IN + 255) / 256, 256>>>(loc, tim, emb_loc, emb_tim);
    k_hist_feat<<<NHIST, 128>>>(hloc, htim, hcnt, emb_loc, emb_tim);

    // history = tanh(xcat @ fc_attn_w^T + b)   [tiled fp32]
    k_gemm_hist<<<dim3(NHIST / 64, HID / 64), 256>>>(fc_attn_w, fc_attn_b);
    // gi = x @ w_ih^T + b_ih                    [tiled fp32]
    k_gemm_gi<<<dim3(S_LEN / 64, GI_N / 64), 256>>>(w_ih, b_ih);

    // GRU scan: ONE persistent launch, flag-vector barrier
    k_gru<<<GRU_BLOCKS, 256>>>(w_hh, b_hh);

    // scores = q @ hist^T; softmax; ctx = attn @ hist
    k_gemm_scores<<<dim3(TARGET / 64, NHIST / 64), 256>>>();
    k_softmax<<<TARGET, 256>>>();
    k_gemm_ctx<<<dim3(TARGET / 64, HID / 64), 256>>>();

    k_build_out<<<(TARGET * OUTK + 255) / 256, 256>>>(emb_uid, uid);
    k_convert_w<<<4096, 256>>>(fc_final_w);
    k_final<<<dim3(TARGET / FBM, (LOCN + FBN - 1) / FBN), 256>>>(fc_final_b, Y);
    k_logsoftmax<<<TARGET, 256>>>(Y);
}

// round 17
// speedup vs baseline: 1.0889x; 1.0889x over previous
#include <cuda_runtime.h>
#include <cuda_bf16.h>
#include <mma.h>

using namespace nvcuda;

#define S_LEN 2048
#define NHIST 1024
#define LOCN 50000
#define D_LOCE 512
#define D_TIME 64
#define D_UIDE 64
#define HID 512
#define D_IN 576
#define TARGET 1024
#define GI_N 1536
#define OUTK 1088
#define GRU_BLOCKS 32

// ---------------- device scratch ----------------
// RULE: device globals are ONLY referenced inside kernels. Host code NEVER
// passes their address as a kernel argument (host symbol shadow + GB300 ATS
// silently reads/writes host memory -> zeros). Harness pointers only.
__device__ float g_x[S_LEN * D_IN];
__device__ float g_xcat[NHIST * D_IN];
__device__ float g_hist[NHIST * HID];
__device__ float g_gi[S_LEN * GI_N];
__device__ float g_h[2 * HID];
__device__ float g_q[TARGET * HID];
__device__ float g_scores[TARGET * NHIST];
__device__ float g_ctx[TARGET * HID];
__device__ __nv_bfloat16 g_outbh[TARGET * OUTK];
__device__ __nv_bfloat16 g_Wbh[(size_t)LOCN * OUTK];
__device__ int g_off[NHIST];
__device__ __align__(128) volatile unsigned g_flag[GRU_BLOCKS];

__global__ void k_init() {
    int t = threadIdx.x;
    for (int i = t; i < 2 * HID; i += blockDim.x) g_h[i] = 0.f;
    if (t < GRU_BLOCKS) g_flag[t] = 0u;
}

__global__ void k_offsets(const int* __restrict__ cnt) {
    __shared__ int sc[NHIST];
    int t = threadIdx.x;
    sc[t] = cnt[t];
    __syncthreads();
    int s = 0;
    for (int j = 0; j < t; j++) s += sc[j];
    g_off[t] = s;
}

__global__ void k_build_x(const int* __restrict__ loc, const int* __restrict__ tim,
                          const float* __restrict__ emb_loc, const float* __restrict__ emb_tim) {
    int idx = blockIdx.x * blockDim.x + threadIdx.x;
    if (idx >= S_LEN * D_IN) return;
    int s = idx / D_IN, d = idx - s * D_IN;
    float v;
    if (d < D_LOCE) v = emb_loc[(size_t)loc[s] * D_LOCE + d];
    else            v = emb_tim[(size_t)tim[s] * D_TIME + (d - D_LOCE)];
    g_x[idx] = v;
}

__global__ void k_hist_feat(const int* __restrict__ hloc, const int* __restrict__ htim,
                            const int* __restrict__ hcnt,
                            const float* __restrict__ emb_loc, const float* __restrict__ emb_tim) {
    int b = blockIdx.x, t = threadIdx.x;
    int off = g_off[b];
    int cnt = hcnt[b];
    float inv = (cnt > 0) ? 1.f / (float)cnt : 0.f;
    for (int d = t; d < D_LOCE; d += blockDim.x) {
        float s = 0.f;
        for (int r = 0; r < cnt; r++)
            s += emb_loc[(size_t)hloc[off + r] * D_LOCE + d];
        g_xcat[b * D_IN + d] = s * inv;
    }
    for (int d = t; d < D_TIME; d += blockDim.x)
        g_xcat[b * D_IN + D_LOCE + d] = emb_tim[(size_t)htim[off] * D_TIME + d];
}

// ---------------- tiled fp32 GEMM bodies (device-side; pointers bound by the
// CALLING KERNEL, never by host) ----------------
// C[M,N] = A[M,K] @ B[N,K]^T (+bias) (EPI 1 = tanh). M,N mult of 64, K mult of 16.
template <int EPI>
__device__ __forceinline__ void gemm_nt_body(const float* __restrict__ A,
                                             const float* __restrict__ B,
                                             const float* __restrict__ bias,
                                             float* __restrict__ C,
                                             int M, int N, int K) {
    __shared__ float As[16][64];
    __shared__ float Bs[16][64];
    int m0 = blockIdx.x * 64, n0 = blockIdx.y * 64;
    int t = threadIdx.x;
    int tx = t % 16, ty = t / 16;
    int lr = t / 4, lq = t % 4;
    float acc[4][4] = {};
    for (int k0 = 0; k0 < K; k0 += 16) {
        float4 av = *(const float4*)&A[(size_t)(m0 + lr) * K + k0 + lq * 4];
        float4 bv = *(const float4*)&B[(size_t)(n0 + lr) * K + k0 + lq * 4];
        As[lq * 4 + 0][lr] = av.x; As[lq * 4 + 1][lr] = av.y;
        As[lq * 4 + 2][lr] = av.z; As[lq * 4 + 3][lr] = av.w;
        Bs[lq * 4 + 0][lr] = bv.x; Bs[lq * 4 + 1][lr] = bv.y;
        Bs[lq * 4 + 2][lr] = bv.z; Bs[lq * 4 + 3][lr] = bv.w;
        __syncthreads();
#pragma unroll
        for (int k = 0; k < 16; k++) {
            float a[4], b[4];
#pragma unroll
            for (int i = 0; i < 4; i++) { a[i] = As[k][ty * 4 + i]; b[i] = Bs[k][tx * 4 + i]; }
#pragma unroll
            for (int i = 0; i < 4; i++)
#pragma unroll
                for (int j = 0; j < 4; j++) acc[i][j] += a[i] * b[j];
        }
        __syncthreads();
    }
#pragma unroll
    for (int i = 0; i < 4; i++)
#pragma unroll
        for (int j = 0; j < 4; j++) {
            int m = m0 + ty * 4 + i, n = n0 + tx * 4 + j;
            float v = acc[i][j];
            if (bias) v += bias[n];
            if (EPI == 1) v = tanhf(v);
            C[(size_t)m * N + n] = v;
        }
}

// C[M,N] = A[M,K] @ B[K,N]. M,N mult of 64, K mult of 16.
__device__ __forceinline__ void gemm_nn_body(const float* __restrict__ A,
                                             const float* __restrict__ B,
                                             float* __restrict__ C,
                                             int M, int N, int K) {
    __shared__ float As[16][64];
    __shared__ float Bs[16][64];
    int m0 = blockIdx.x * 64, n0 = blockIdx.y * 64;
    int t = threadIdx.x;
    int tx = t % 16, ty = t / 16;
    int lr = t / 4, lq = t % 4;
    int bk = t / 16, bn = t % 16;
    float acc[4][4] = {};
    for (int k0 = 0; k0 < K; k0 += 16) {
        float4 av = *(const float4*)&A[(size_t)(m0 + lr) * K + k0 + lq * 4];
        As[lq * 4 + 0][lr] = av.x; As[lq * 4 + 1][lr] = av.y;
        As[lq * 4 + 2][lr] = av.z; As[lq * 4 + 3][lr] = av.w;
        float4 bv = *(const float4*)&B[(size_t)(k0 + bk) * N + n0 + bn * 4];
        *(float4*)&Bs[bk][bn * 4] = bv;
        __syncthreads();
#pragma unroll
        for (int k = 0; k < 16; k++) {
            float a[4], b[4];
#pragma unroll
            for (int i = 0; i < 4; i++) { a[i] = As[k][ty * 4 + i]; b[i] = Bs[k][tx * 4 + i]; }
#pragma unroll
            for (int i = 0; i < 4; i++)
#pragma unroll
                for (int j = 0; j < 4; j++) acc[i][j] += a[i] * b[j];
        }
        __syncthreads();
    }
#pragma unroll
    for (int i = 0; i < 4; i++)
#pragma unroll
        for (int j = 0; j < 4; j++)
            C[(size_t)(m0 + ty * 4 + i) * N + n0 + tx * 4 + j] = acc[i][j];
}

// wrappers: device globals bound INSIDE the kernel; harness pointers as args
__global__ void __launch_bounds__(256) k_gemm_hist(const float* __restrict__ fa,
                                                   const float* __restrict__ fab) {
    gemm_nt_body<1>(g_xcat, fa, fab, g_hist, NHIST, HID, D_IN);
}
__global__ void __launch_bounds__(256) k_gemm_gi(const float* __restrict__ w_ih,
                                                 const float* __restrict__ b_ih) {
    gemm_nt_body<0>(g_x, w_ih, b_ih, g_gi, S_LEN, GI_N, D_IN);
}
__global__ void __launch_bounds__(256) k_gemm_scores() {
    gemm_nt_body<0>(g_q, g_hist, (const float*)0, g_scores, TARGET, NHIST, HID);
}
__global__ void __launch_bounds__(256) k_gemm_ctx() {
    gemm_nn_body(g_scores, g_hist, g_ctx, TARGET, HID, NHIST);
}

// ---------------- persistent GRU scan, flag-vector barrier ----------------
// 32 blocks x 256 threads. Block b owns hidden lanes [16b, 16b+16).
// rid = t/4 picks one of 48 gh rows, p = t%4 a 128-wide column quarter (regs).
// Barrier: block publishes g_flag[b] = step+1 after its h-slice store+fence;
// threads t<32 each poll one flag (one cache line, one transaction per poll).
__global__ void __launch_bounds__(256) k_gru(const float* __restrict__ w_hh,
                                             const float* __restrict__ b_hh) {
    __shared__ float h_s[HID];
    __shared__ float part[48][4];
    __shared__ float sgh[48];
    int b = blockIdx.x, t = threadIdx.x;
    int jbase = b * 16;
    int rid = t >> 2;
    int p = t & 3;
    bool active = (rid < 48);

    float wv[128];
    if (active) {
        int gate = rid >> 4;
        int jj = rid & 15;
        int grow = gate * HID + jbase + jj;
        const float* wr = w_hh + (size_t)grow * HID + p * 128;
#pragma unroll
        for (int i = 0; i < 128; i++) wv[i] = wr[i];
    }
    float bh0 = 0.f, bh1 = 0.f, bh2 = 0.f;
    if (t < 16) {
        bh0 = b_hh[jbase + t];
        bh1 = b_hh[HID + jbase + t];
        bh2 = b_hh[2 * HID + jbase + t];
    }

    for (int step = 0; step < S_LEN; step++) {
        float ir = 0.f, iz = 0.f, inn = 0.f;
        if (t < 16) {
            const float* git = g_gi + (size_t)step * GI_N;
            ir  = git[jbase + t];
            iz  = git[HID + jbase + t];
            inn = git[2 * HID + jbase + t];
        }
        const float* hrd = g_h + (step & 1) * HID;
        float* hwr = g_h + ((step + 1) & 1) * HID;
        if (t < 128) {
            float4 hv = __ldcg((const float4*)hrd + t);
            ((float4*)h_s)[t] = hv;
        }
        __syncthreads();

        if (active) {
            const float4* hp4 = (const float4*)(h_s + p * 128);
            float s0 = 0.f, s1 = 0.f, s2 = 0.f, s3 = 0.f;
#pragma unroll
            for (int i = 0; i < 32; i++) {
                float4 hv = hp4[i];
                s0 = fmaf(wv[4 * i + 0], hv.x, s0);
                s1 = fmaf(wv[4 * i + 1], hv.y, s1);
                s2 = fmaf(wv[4 * i + 2], hv.z, s2);
                s3 = fmaf(wv[4 * i + 3], hv.w, s3);
            }
            part[rid][p] = (s0 + s1) + (s2 + s3);
        }
        __syncthreads();
        if (t < 48) sgh[t] = (part[t][0] + part[t][1]) + (part[t][2] + part[t][3]);
        __syncthreads();

        if (t < 16) {
            float r = 1.f / (1.f + expf(-(ir + sgh[t] + bh0)));
            float z = 1.f / (1.f + expf(-(iz + sgh[16 + t] + bh1)));
            float n = tanhf(inn + r * (sgh[32 + t] + bh2));
            float hold = h_s[jbase + t];
            float hnew = (1.f - z) * n + z * hold;
            hwr[jbase + t] = hnew;
            if (step >= S_LEN - TARGET)
                g_q[(size_t)(step - (S_LEN - TARGET)) * HID + jbase + t] = hnew;
            __threadfence();
        }
        __syncthreads();
        if (t == 0) g_flag[b] = (unsigned)(step + 1);
        if (t < GRU_BLOCKS) {
            while (g_flag[t] < (unsigned)(step + 1)) {}
        }
        __threadfence();
        __syncthreads();
    }
}

// row softmax of scores [TARGET, NHIST]
__global__ void __launch_bounds__(256) k_softmax() {
    __shared__ float red[256];
    int r = blockIdx.x, t = threadIdx.x;
    float* row = g_scores + (size_t)r * NHIST;
    float m = -1e30f;
    for (int i = t; i < NHIST; i += 256) m = fmaxf(m, row[i]);
    red[t] = m; __syncthreads();
    for (int o = 128; o; o >>= 1) { if (t < o) red[t] = fmaxf(red[t], red[t + o]); __syncthreads(); }
    m = red[0];
    __syncthreads();
    float s = 0.f;
    for (int i = t; i < NHIST; i += 256) { float e = __expf(row[i] - m); row[i] = e; s += e; }
    red[t] = s; __syncthreads();
    for (int o = 128; o; o >>= 1) { if (t < o) red[t] += red[t + o]; __syncthreads(); }
    float inv = 1.f / red[0];
    for (int i = t; i < NHIST; i += 256) row[i] *= inv;
}

__global__ void k_build_out(const float* __restrict__ emb_uid, const int* __restrict__ uid) {
    int idx = blockIdx.x * blockDim.x + threadIdx.x;
    if (idx >= TARGET * OUTK) return;
    int r = idx / OUTK, c = idx - r * OUTK;
    float v;
    if (c < HID) v = g_q[(size_t)r * HID + c];
    else if (c < 2 * HID) v = g_ctx[(size_t)r * HID + (c - HID)];
    else v = emb_uid[(size_t)uid[0] * D_UIDE + (c - 2 * HID)];
    g_outbh[idx] = __float2bfloat16(v);
}

__global__ void k_convert_w(const float* __restrict__ W) {
    size_t n4 = (size_t)LOCN * OUTK / 4;
    for (size_t i = (size_t)blockIdx.x * blockDim.x + threadIdx.x; i < n4;
         i += (size_t)gridDim.x * blockDim.x) {
        float4 v = ((const float4*)W)[i];
        __nv_bfloat162* oh = (__nv_bfloat162*)g_Wbh;
        oh[2 * i]     = __floats2bfloat162_rn(v.x, v.y);
        oh[2 * i + 1] = __floats2bfloat162_rn(v.z, v.w);
    }
}

// ---------------- final bf16 wmma GEMM (single pass): Y = out @ W^T + bias ----
#define FBM 64
#define FBN 128
#define FBK 32
__global__ void __launch_bounds__(256) k_final(const float* __restrict__ bias, float* __restrict__ Y) {
    __shared__ __nv_bfloat16 As[FBM * FBK];
    __shared__ __nv_bfloat16 Bs[FBN * FBK];
    __shared__ float Cs[FBM * FBN];
    int m0 = blockIdx.x * FBM;
    int n0 = blockIdx.y * FBN;
    int t = threadIdx.x;
    int warp = t / 32;
    int wm = warp % 2, wn = warp / 2;

    wmma::fragment<wmma::accumulator, 16, 16, 16, float> acc[2][2];
#pragma unroll
    for (int i = 0; i < 2; i++)
#pragma unroll
        for (int j = 0; j < 2; j++) wmma::fill_fragment(acc[i][j], 0.f);

    for (int k0 = 0; k0 < OUTK; k0 += FBK) {
        {
            int r = t / 4, c = (t % 4) * 8;
            *(uint4*)&As[r * FBK + c] =
                *(const uint4*)&g_outbh[(size_t)(m0 + r) * OUTK + k0 + c];
        }
#pragma unroll
        for (int i = 0; i < 2; i++) {
            int idx = t + i * 256;
            int r = idx / 4, c = (idx % 4) * 8;
            int n = n0 + r;
            uint4 v = make_uint4(0u, 0u, 0u, 0u);
            if (n < LOCN)
                v = *(const uint4*)&g_Wbh[(size_t)n * OUTK + k0 + c];
            *(uint4*)&Bs[r * FBK + c] = v;
        }
        __syncthreads();
#pragma unroll
        for (int kk = 0; kk < FBK; kk += 16) {
            wmma::fragment<wmma::matrix_a, 16, 16, 16, __nv_bfloat16, wmma::row_major> a0, a1;
            wmma::fragment<wmma::matrix_b, 16, 16, 16, __nv_bfloat16, wmma::col_major> b0, b1;
            wmma::load_matrix_sync(a0, &As[(wm * 32 + 0) * FBK + kk], FBK);
            wmma::load_matrix_sync(a1, &As[(wm * 32 + 16) * FBK + kk], FBK);
            wmma::load_matrix_sync(b0, &Bs[(wn * 32 + 0) * FBK + kk], FBK);
            wmma::load_matrix_sync(b1, &Bs[(wn * 32 + 16) * FBK + kk], FBK);
            wmma::mma_sync(acc[0][0], a0, b0, acc[0][0]);
            wmma::mma_sync(acc[0][1], a0, b1, acc[0][1]);
            wmma::mma_sync(acc[1][0], a1, b0, acc[1][0]);
            wmma::mma_sync(acc[1][1], a1, b1, acc[1][1]);
        }
        __syncthreads();
    }
#pragma unroll
    for (int i = 0; i < 2; i++)
#pragma unroll
        for (int j = 0; j < 2; j++)
            wmma::store_matrix_sync(&Cs[(wm * 32 + i * 16) * FBN + wn * 32 + j * 16],
                                    acc[i][j], FBN, wmma::mem_row_major);
    __syncthreads();
    for (int idx = t; idx < FBM * FBN; idx += 256) {
        int r = idx / FBN, c = idx - r * FBN;
        int n = n0 + c;
        if (n < LOCN)
            Y[(size_t)(m0 + r) * LOCN + n] = Cs[idx] + bias[n];
    }
}

// ---------------- online (single-read) row log_softmax on Y [1024, 50000] ----
__global__ void __launch_bounds__(256) k_logsoftmax(float* __restrict__ Y) {
    __shared__ float rm[256], rs[256];
    int r = blockIdx.x, t = threadIdx.x;
    float* row = Y + (size_t)r * LOCN;
    const int n4 = LOCN / 4;
    float m = -1e30f, s = 0.f;
    for (int i = t; i < n4; i += 256) {
        float4 v = ((const float4*)row)[i];
        float mv = fmaxf(fmaxf(v.x, v.y), fmaxf(v.z, v.w));
        if (mv > m) { s *= __expf(m - mv); m = mv; }
        s += __expf(v.x - m) + __expf(v.y - m) + __expf(v.z - m) + __expf(v.w - m);
    }
    rm[t] = m; rs[t] = s; __syncthreads();
    for (int o = 128; o; o >>= 1) {
        if (t < o) {
            float m2 = fmaxf(rm[t], rm[t + o]);
            rs[t] = rs[t] * __expf(rm[t] - m2) + rs[t + o] * __expf(rm[t + o] - m2);
            rm[t] = m2;
        }
        __syncthreads();
    }
    float lse = rm[0] + logf(rs[0]);
    for (int i = t; i < n4; i += 256) {
        float4 v = ((float4*)row)[i];
        v.x -= lse; v.y -= lse; v.z -= lse; v.w -= lse;
        ((float4*)row)[i] = v;
    }
}

extern "C" void kernel_launch(void* const* d_in, const int* in_sizes, int n_in,
                              void* d_out, int out_size) {
    const int *loc = 0, *tim = 0, *hloc = 0, *htim = 0, *hcnt = 0, *uid = 0;
    const float *emb_loc = 0, *emb_tim = 0, *emb_uid = 0;
    const float *fc_attn_w = 0, *fc_attn_b = 0;
    const float *w_ih = 0, *w_hh = 0, *b_ih = 0, *b_hh = 0;
    const float *fc_final_w = 0, *fc_final_b = 0;
    int c2048 = 0, c4096 = 0, c1536 = 0, c1 = 0;
    for (int i = 0; i < n_in; i++) {
        long s = in_sizes[i];
        const void* p = d_in[i];
        if      (s == 2048)      { if (c2048++ == 0) loc = (const int*)p; else tim = (const int*)p; }
        else if (s == 4096)      { if (c4096++ == 0) hloc = (const int*)p; else htim = (const int*)p; }
        else if (s == 1024)      hcnt = (const int*)p;
        else if (s == 1)         { if (c1++ == 0) uid = (const int*)p; }
        else if (s == 25600000)  emb_loc = (const float*)p;
        else if (s == 3072)      emb_tim = (const float*)p;
        else if (s == 64000)     emb_uid = (const float*)p;
        else if (s == 294912)    fc_attn_w = (const float*)p;
        else if (s == 512)       fc_attn_b = (const float*)p;
        else if (s == 884736)    w_ih = (const float*)p;
        else if (s == 786432)    w_hh = (const float*)p;
        else if (s == 1536)      { if (c1536++ == 0) b_ih = (const float*)p; else b_hh = (const float*)p; }
        else if (s == 54400000)  fc_final_w = (const float*)p;
        else if (s == 50000)     fc_final_b = (const float*)p;
    }
    float* Y = (float*)d_out;

    k_init<<<1, 256>>>();
    k_offsets<<<1, NHIST>>>(hcnt);
    k_build_x<<<(S_LEN * D_IN + 255) / 256, 256>>>(loc, tim, emb_loc, emb_tim);
    k_hist_feat<<<NHIST, 128>>>(hloc, htim, hcnt, emb_loc, emb_tim);

    // history = tanh(xcat @ fc_attn_w^T + b)   [tiled fp32]
    k_gemm_hist<<<dim3(NHIST / 64, HID / 64), 256>>>(fc_attn_w, fc_attn_b);
    // gi = x @ w_ih^T + b_ih                    [tiled fp32]
    k_gemm_gi<<<dim3(S_LEN / 64, GI_N / 64), 256>>>(w_ih, b_ih);

    // GRU scan: ONE persistent launch, flag-vector barrier
    k_gru<<<GRU_BLOCKS, 256>>>(w_hh, b_hh);

    // scores = q @ hist^T; softmax; ctx = attn @ hist
    k_gemm_scores<<<dim3(TARGET / 64, NHIST / 64), 256>>>();
    k_softmax<<<TARGET, 256>>>();
    k_gemm_ctx<<<dim3(TARGET / 64, HID / 64), 256>>>();

    k_build_out<<<(TARGET * OUTK + 255) / 256, 256>>>(emb_uid, uid);
    k_convert_w<<<4096, 256>>>(fc_final_w);
    k_final<<<dim3(TARGET / FBM, (LOCN + FBN - 1) / FBN), 256>>>(fc_final_b, Y);
    k_logsoftmax<<<TARGET, 256>>>(Y);
}